// round 3
// baseline (speedup 1.0000x reference)
#include <cuda_runtime.h>
#include <math.h>

// Fused differentiable JPEG. One CTA = 128x16 pixel strip = 8 tiles of 16x16.
// 384 threads = 48 blocks (8 tiles x [4 Y + Cb + Cr]) x 8 rows.
// Each thread owns one 8-element row/column of an 8x8 block; all four 1-D
// transform passes run in registers with compile-time cosine constants.
// Shared memory used only for: staging planes, 2 transposes, quant tables.

__constant__ float cQTY[64] = {
  16,11,10,16,24,40,51,61,
  12,12,14,19,26,58,60,55,
  14,13,16,24,40,57,69,56,
  14,17,22,29,51,87,80,62,
  18,22,37,56,68,109,103,77,
  24,35,55,64,81,104,113,92,
  49,64,78,87,103,121,120,101,
  72,92,95,98,112,100,103,99};

__constant__ float cQTC[64] = {
  17,18,24,47,99,99,99,99,
  18,21,26,66,99,99,99,99,
  24,26,56,99,99,99,99,99,
  47,66,99,99,99,99,99,99,
  99,99,99,99,99,99,99,99,
  99,99,99,99,99,99,99,99,
  99,99,99,99,99,99,99,99,
  99,99,99,99,99,99,99,99};

// cos(k*pi/16), k=0..7, rounded-from-double literals
__host__ __device__ constexpr float cb_(int k) {
  return k==0 ? 1.0f
       : k==1 ? 0.98078528040323044913f
       : k==2 ? 0.92387953251128675613f
       : k==3 ? 0.83146961230254523708f
       : k==4 ? 0.70710678118654752440f
       : k==5 ? 0.55557023301960222474f
       : k==6 ? 0.38268343236508977173f
       :        0.19509032201612826785f;
}
// cos(m*pi/16) for any integer m >= 0
__host__ __device__ constexpr float cosm(int m) {
  return (m & 31) > 16 ? cosm(32 - (m & 31))
       : (m & 31) == 8 ? 0.0f
       : (m & 31) < 8  ? cb_(m & 31)
       :                 -cb_(16 - (m & 31));
}
// C[u][x] = cos((2x+1)*u*pi/16) -- folds to an immediate in unrolled loops
#define CT(u, x) (cosm((2*(x)+1)*(u)))

__device__ __forceinline__ float poly_round_f(float x) {
  float r = rintf(x);               // round-half-to-even == jnp.round
  float d = x - r;
  return r + d * d * d;
}
__device__ __forceinline__ float poly_floor_f(float x) {
  return poly_round_f(x - 0.5f);
}
__device__ __forceinline__ float diff_clip_f(float x, float lo, float hi) {
  float out = x;
  if (x > hi) out = -0.02f * (expf(hi - x) - 1.0f) + hi;
  if (x < lo) out =  0.02f * (expf(x - lo) - 1.0f) + lo;
  return out;
}

#define PITCH 132   // padded row pitch (floats) for 128-wide plane staging

__global__ __launch_bounds__(384)
void jpeg_fused(const float* __restrict__ in, float* __restrict__ out) {
  const int  W     = 512;
  const long plane = 512L * 512L;

  const int t  = threadIdx.x;
  const int sx = blockIdx.x;   // strip 0..3 (128 cols each)
  const int ty = blockIdx.y;   // tile row 0..31
  const int b  = blockIdx.z;   // batch

  __shared__ float yS [16 * PITCH];   // Y-128 (in) / decoded Y+128 (out)
  __shared__ float cbS[16 * PITCH];   // Cb full-res (in) / decoded Cb+128 rows 0..7 (out)
  __shared__ float crS[16 * PITCH];
  __shared__ float tr [48 * 72];      // transpose scratch: block stride 72, row pitch 9
  __shared__ float qtS[128];          // [0..63]=Y table, [64..127]=C table

  const float* inb  = in  + (long)b * 3 * plane + (long)(ty * 16) * W + sx * 128;
  float*       outb = out + (long)b * 3 * plane + (long)(ty * 16) * W + sx * 128;

  // ---- quant tables (q=50 -> s = poly_floor(100) = 99.875 exactly) ----
  if (t < 128) {
    int c = t >> 6, e = t & 63;
    const float s = 99.875f;
    float base = c ? cQTC[e] : cQTY[e];
    float tq = poly_floor_f((base * s + 50.0f) / 100.0f);
    qtS[c * 64 + e] = diff_clip_f(tq, 1.0f, 255.0f);
  }

  // ---- Phase 1: load 128x16 RGB, clip, scale, RGB->YCbCr, stage planes ----
  #pragma unroll
  for (int k = 0; k < 2; k++) {
    int q = t + 384 * k;
    if (q < 512) {                      // 512 quads of 4 pixels
      int row = q >> 5;
      int c4  = (q & 31) * 4;
      const float* p = inb + (long)row * W + c4;
      float4 R = *(const float4*)p;
      float4 G = *(const float4*)(p + plane);
      float4 B = *(const float4*)(p + 2 * plane);
      float rr[4] = {R.x, R.y, R.z, R.w};
      float gg[4] = {G.x, G.y, G.z, G.w};
      float bb[4] = {B.x, B.y, B.z, B.w};
      float yv[4], cbv[4], crv[4];
      #pragma unroll
      for (int l = 0; l < 4; l++) {
        float r  = fminf(fmaxf(rr[l], -1.0f), 1.0f);
        float g  = fminf(fmaxf(gg[l], -1.0f), 1.0f);
        float bl = fminf(fmaxf(bb[l], -1.0f), 1.0f);
        r  = (r  + 1.0f) * 255.0f / 2.0f;
        g  = (g  + 1.0f) * 255.0f / 2.0f;
        bl = (bl + 1.0f) * 255.0f / 2.0f;
        yv[l]  =  0.299f    * r + 0.587f    * g + 0.114f    * bl - 128.0f;
        cbv[l] = -0.168736f * r - 0.331264f * g + 0.5f      * bl + 128.0f;
        crv[l] =  0.5f      * r - 0.418688f * g - 0.081312f * bl + 128.0f;
      }
      float* yp = yS + row * PITCH + c4;
      *(float4*)yp                       = make_float4(yv[0],  yv[1],  yv[2],  yv[3]);
      *(float4*)(cbS + row * PITCH + c4) = make_float4(cbv[0], cbv[1], cbv[2], cbv[3]);
      *(float4*)(crS + row * PITCH + c4) = make_float4(crv[0], crv[1], crv[2], crv[3]);
    }
  }
  __syncthreads();

  // ---- Phase 2: per-thread block-row pipeline ----
  const int bk   = t >> 3;        // block 0..47 (type-major: warp = same type)
  const int r    = t & 7;         // row / col within block owned by this thread
  const int type = bk >> 3;       // 0..3 = Y quadrant, 4 = Cb, 5 = Cr
  const int tt   = bk & 7;        // tile within strip
  float* trb = tr + bk * 72;

  // Gather the thread's input row X[0..7]
  float X[8];
  int qrow = 0, col0 = 0;
  if (type < 4) {
    qrow = (type >> 1) * 8 + r;
    col0 = tt * 16 + (type & 1) * 8;
    const float* yp = yS + qrow * PITCH + col0;
    float4 a = *(const float4*)yp;
    float4 c = *(const float4*)(yp + 4);
    X[0]=a.x; X[1]=a.y; X[2]=a.z; X[3]=a.w;
    X[4]=c.x; X[5]=c.y; X[6]=c.z; X[7]=c.w;
  } else {
    const float* src = (type == 4) ? cbS : crS;
    const float* r0p = src + (2 * r) * PITCH + tt * 16;
    const float* r1p = r0p + PITCH;
    #pragma unroll
    for (int c = 0; c < 8; c++)
      X[c] = ((r0p[2*c] + r0p[2*c+1]) + (r1p[2*c] + r1p[2*c+1])) * 0.25f - 128.0f;
  }

  // Pass 1 (row DCT): T[v] = sum_y X[y] * C[v][y]
  float T[8];
  #pragma unroll
  for (int v = 0; v < 8; v++) {
    float s = X[0] * CT(v, 0);
    #pragma unroll
    for (int y = 1; y < 8; y++) s = fmaf(X[y], CT(v, y), s);
    T[v] = s;
  }

  // Transpose 1 (conflict-free: stride 72/pitch 9)
  #pragma unroll
  for (int v = 0; v < 8; v++) trb[r * 9 + v] = T[v];
  __syncthreads();
  float U[8];
  #pragma unroll
  for (int x = 0; x < 8; x++) U[x] = trb[x * 9 + r];

  // Pass 2 (col DCT) + quant/dequant; thread owns column v=r of F
  const float isq2 = 0.70710678118654752440f;
  float q1 = ((r == 0) ? isq2 : 1.0f) * 0.25f;            // 0.25*a[u!=0]*a[v]
  float q0 = ((r == 0) ? 0.5f  : isq2) * 0.25f;           // 0.25*a[0]*a[v]
  const float* qtp = qtS + ((type < 4) ? 0 : 64);
  float H[8];
  #pragma unroll
  for (int u = 0; u < 8; u++) {
    float s = U[0] * CT(u, 0);
    #pragma unroll
    for (int x = 1; x < 8; x++) s = fmaf(U[x], CT(u, x), s);
    float su = (u == 0) ? q0 : q1;
    float F  = su * s;                        // full DCT coefficient
    float qv = qtp[u * 8 + r];
    float c  = poly_round_f(F / qv);          // quantize
    H[u] = su * (c * qv);                     // dequant * 0.25*alpha2 (IDCT input)
  }

  // Pass 3 (col IDCT, no transpose needed): G[x] = sum_u H[u] * C[u][x]
  float Gv[8];
  #pragma unroll
  for (int x = 0; x < 8; x++) {
    float s = H[0] * CT(0, x);
    #pragma unroll
    for (int u = 1; u < 8; u++) s = fmaf(H[u], CT(u, x), s);
    Gv[x] = s;
  }

  // Transpose 2
  #pragma unroll
  for (int x = 0; x < 8; x++) trb[x * 9 + r] = Gv[x];
  __syncthreads();
  float P[8];
  #pragma unroll
  for (int v = 0; v < 8; v++) P[v] = trb[r * 9 + v];

  // Pass 4 (row IDCT): pix[y] = sum_v P[v] * C[v][y] + 128, write back
  float pix[8];
  #pragma unroll
  for (int y = 0; y < 8; y++) {
    float s = P[0] * CT(0, y);
    #pragma unroll
    for (int v = 1; v < 8; v++) s = fmaf(P[v], CT(v, y), s);
    pix[y] = s + 128.0f;
  }
  if (type < 4) {
    float* yp = yS + qrow * PITCH + col0;
    *(float4*)yp       = make_float4(pix[0], pix[1], pix[2], pix[3]);
    *(float4*)(yp + 4) = make_float4(pix[4], pix[5], pix[6], pix[7]);
  } else {
    float* cp = ((type == 4) ? cbS : crS) + r * PITCH + tt * 8;
    *(float4*)cp       = make_float4(pix[0], pix[1], pix[2], pix[3]);
    *(float4*)(cp + 4) = make_float4(pix[4], pix[5], pix[6], pix[7]);
  }
  __syncthreads();

  // ---- Phase 3: assemble RGB, diff_clip, rescale, store ----
  #pragma unroll
  for (int k = 0; k < 2; k++) {
    int q = t + 384 * k;
    if (q < 512) {
      int row = q >> 5;
      int c4  = (q & 31) * 4;
      float rr[4], gg[4], bb[4];
      #pragma unroll
      for (int l = 0; l < 4; l++) {
        int j  = c4 + l;
        int cc = (j >> 4) * 8 + ((j & 15) >> 1);
        float Y  = yS [row * PITCH + j];
        float cbv= cbS[(row >> 1) * PITCH + cc] - 128.0f;
        float crv= crS[(row >> 1) * PITCH + cc] - 128.0f;
        float R  = Y + 1.402f    * crv;
        float G  = Y - 0.344136f * cbv - 0.714136f * crv;
        float B  = Y + 1.772f    * cbv;
        R = diff_clip_f(R, 0.0f, 255.0f);
        G = diff_clip_f(G, 0.0f, 255.0f);
        B = diff_clip_f(B, 0.0f, 255.0f);
        rr[l] = fminf(fmaxf(R * 2.0f / 255.0f - 1.0f, -1.0f), 1.0f);
        gg[l] = fminf(fmaxf(G * 2.0f / 255.0f - 1.0f, -1.0f), 1.0f);
        bb[l] = fminf(fmaxf(B * 2.0f / 255.0f - 1.0f, -1.0f), 1.0f);
      }
      float* p = outb + (long)row * W + c4;
      *(float4*)p               = make_float4(rr[0], rr[1], rr[2], rr[3]);
      *(float4*)(p + plane)     = make_float4(gg[0], gg[1], gg[2], gg[3]);
      *(float4*)(p + 2 * plane) = make_float4(bb[0], bb[1], bb[2], bb[3]);
    }
  }
}

extern "C" void kernel_launch(void* const* d_in, const int* in_sizes, int n_in,
                              void* d_out, int out_size) {
  const float* in = (const float*)d_in[0];
  float* out = (float*)d_out;
  int B = in_sizes[0] / (3 * 512 * 512);
  dim3 grid(4, 32, B);
  jpeg_fused<<<grid, 384>>>(in, out);
}

// round 5
// speedup vs baseline: 1.1317x; 1.1317x over previous
#include <cuda_runtime.h>
#include <math.h>

// Fused differentiable JPEG. One CTA = 128x16 pixel strip = 8 tiles of 16x16.
// 384 threads = 48 blocks (8 tiles x [4 Y + Cb + Cr]) x 8 rows.
// R3/R4: branchless single-MUFU diff_clip, reciprocal-multiply quantization.

__constant__ float cQTY[64] = {
  16,11,10,16,24,40,51,61,
  12,12,14,19,26,58,60,55,
  14,13,16,24,40,57,69,56,
  14,17,22,29,51,87,80,62,
  18,22,37,56,68,109,103,77,
  24,35,55,64,81,104,113,92,
  49,64,78,87,103,121,120,101,
  72,92,95,98,112,100,103,99};

__constant__ float cQTC[64] = {
  17,18,24,47,99,99,99,99,
  18,21,26,66,99,99,99,99,
  24,26,56,99,99,99,99,99,
  47,66,99,99,99,99,99,99,
  99,99,99,99,99,99,99,99,
  99,99,99,99,99,99,99,99,
  99,99,99,99,99,99,99,99,
  99,99,99,99,99,99,99,99};

// cos(k*pi/16), k=0..7
__host__ __device__ constexpr float cb_(int k) {
  return k==0 ? 1.0f
       : k==1 ? 0.98078528040323044913f
       : k==2 ? 0.92387953251128675613f
       : k==3 ? 0.83146961230254523708f
       : k==4 ? 0.70710678118654752440f
       : k==5 ? 0.55557023301960222474f
       : k==6 ? 0.38268343236508977173f
       :        0.19509032201612826785f;
}
__host__ __device__ constexpr float cosm(int m) {
  return (m & 31) > 16 ? cosm(32 - (m & 31))
       : (m & 31) == 8 ? 0.0f
       : (m & 31) < 8  ? cb_(m & 31)
       :                 -cb_(16 - (m & 31));
}
#define CT(u, x) (cosm((2*(x)+1)*(u)))

__device__ __forceinline__ float poly_round_f(float x) {
  float r = rintf(x);               // round-half-to-even == jnp.round
  float d = x - r;
  return r + d * d * d;
}
__device__ __forceinline__ float poly_floor_f(float x) {
  return poly_round_f(x - 0.5f);
}
// Branchless diff_clip: identical to reference on all three regions.
//   above: out = hi + 0.02*(1-exp(-(x-hi)))   below: out = lo - 0.02*(1-exp(x-lo))
__device__ __forceinline__ float diff_clip_f(float x, float lo, float hi) {
  float c = fminf(fmaxf(x, lo), hi);
  float d = x - c;                  // >0 above, <0 below, 0 inside
  float e = __expf(-fabsf(d));
  return fmaf(copysignf(0.02f, d), 1.0f - e, c);
}
// Exact-exp version for the (tiny) quant-table setup.
__device__ __forceinline__ float diff_clip_exact(float x, float lo, float hi) {
  float out = x;
  if (x > hi) out = -0.02f * (expf(hi - x) - 1.0f) + hi;
  if (x < lo) out =  0.02f * (expf(x - lo) - 1.0f) + lo;
  return out;
}

#define PITCH 132   // padded row pitch (floats) for 128-wide plane staging

__global__ __launch_bounds__(384)
void jpeg_fused(const float* __restrict__ in, float* __restrict__ out) {
  const int  W     = 512;
  const long plane = 512L * 512L;

  const int t  = threadIdx.x;
  const int sx = blockIdx.x;   // strip 0..3
  const int ty = blockIdx.y;   // tile row 0..31
  const int b  = blockIdx.z;   // batch

  __shared__ float yS [16 * PITCH];
  __shared__ float cbS[16 * PITCH];
  __shared__ float crS[16 * PITCH];
  __shared__ float tr [48 * 72];      // transpose scratch (block stride 72, pitch 9)
  __shared__ float qtS[128];          // scaled quant tables (Y | C)
  __shared__ float qrS[128];          // reciprocals of qtS

  const float* inb  = in  + (long)b * 3 * plane + (long)(ty * 16) * W + sx * 128;
  float*       outb = out + (long)b * 3 * plane + (long)(ty * 16) * W + sx * 128;

  // ---- quant tables (q=50 -> s = poly_floor(100) = 99.875 exactly) ----
  if (t < 128) {
    int c = t >> 6, e = t & 63;
    const float s = 99.875f;
    float base = c ? cQTC[e] : cQTY[e];
    float tq = poly_floor_f((base * s + 50.0f) / 100.0f);
    tq = diff_clip_exact(tq, 1.0f, 255.0f);
    qtS[t] = tq;
    qrS[t] = 1.0f / tq;               // exact IEEE reciprocal, once per CTA
  }

  // ---- Phase 1: load 128x16 RGB, clip, scale, RGB->YCbCr, stage planes ----
  #pragma unroll
  for (int k = 0; k < 2; k++) {
    int q = t + 384 * k;
    if (q < 512) {
      int row = q >> 5;
      int c4  = (q & 31) * 4;
      const float* p = inb + (long)row * W + c4;
      float4 R = *(const float4*)p;
      float4 G = *(const float4*)(p + plane);
      float4 B = *(const float4*)(p + 2 * plane);
      float rr[4] = {R.x, R.y, R.z, R.w};
      float gg[4] = {G.x, G.y, G.z, G.w};
      float bb[4] = {B.x, B.y, B.z, B.w};
      float yv[4], cbv[4], crv[4];
      #pragma unroll
      for (int l = 0; l < 4; l++) {
        float r  = fminf(fmaxf(rr[l], -1.0f), 1.0f);
        float g  = fminf(fmaxf(gg[l], -1.0f), 1.0f);
        float bl = fminf(fmaxf(bb[l], -1.0f), 1.0f);
        r  = (r  + 1.0f) * 255.0f / 2.0f;
        g  = (g  + 1.0f) * 255.0f / 2.0f;
        bl = (bl + 1.0f) * 255.0f / 2.0f;
        yv[l]  =  0.299f    * r + 0.587f    * g + 0.114f    * bl - 128.0f;
        cbv[l] = -0.168736f * r - 0.331264f * g + 0.5f      * bl + 128.0f;
        crv[l] =  0.5f      * r - 0.418688f * g - 0.081312f * bl + 128.0f;
      }
      *(float4*)(yS  + row * PITCH + c4) = make_float4(yv[0],  yv[1],  yv[2],  yv[3]);
      *(float4*)(cbS + row * PITCH + c4) = make_float4(cbv[0], cbv[1], cbv[2], cbv[3]);
      *(float4*)(crS + row * PITCH + c4) = make_float4(crv[0], crv[1], crv[2], crv[3]);
    }
  }
  __syncthreads();

  // ---- Phase 2: per-thread block-row pipeline ----
  const int bk   = t >> 3;        // block 0..47
  const int r    = t & 7;         // row within block
  const int type = bk >> 3;       // 0..3 = Y quadrant, 4 = Cb, 5 = Cr
  const int tt   = bk & 7;        // tile within strip
  float* trb = tr + bk * 72;

  float X[8];
  int qrow = 0, col0 = 0;
  if (type < 4) {
    qrow = (type >> 1) * 8 + r;
    col0 = tt * 16 + (type & 1) * 8;
    const float* yp = yS + qrow * PITCH + col0;
    float4 a = *(const float4*)yp;
    float4 c = *(const float4*)(yp + 4);
    X[0]=a.x; X[1]=a.y; X[2]=a.z; X[3]=a.w;
    X[4]=c.x; X[5]=c.y; X[6]=c.z; X[7]=c.w;
  } else {
    const float* src = (type == 4) ? cbS : crS;
    const float* r0p = src + (2 * r) * PITCH + tt * 16;
    const float* r1p = r0p + PITCH;
    #pragma unroll
    for (int c = 0; c < 8; c++)
      X[c] = ((r0p[2*c] + r0p[2*c+1]) + (r1p[2*c] + r1p[2*c+1])) * 0.25f - 128.0f;
  }

  // Pass 1 (row DCT)
  float T[8];
  #pragma unroll
  for (int v = 0; v < 8; v++) {
    float s = X[0] * CT(v, 0);
    #pragma unroll
    for (int y = 1; y < 8; y++) s = fmaf(X[y], CT(v, y), s);
    T[v] = s;
  }

  // Transpose 1
  #pragma unroll
  for (int v = 0; v < 8; v++) trb[r * 9 + v] = T[v];
  __syncthreads();
  float U[8];
  #pragma unroll
  for (int x = 0; x < 8; x++) U[x] = trb[x * 9 + r];

  // Pass 2 (col DCT) + quant/dequant (reciprocal multiply, no FDIV)
  const float isq2 = 0.70710678118654752440f;
  float q1 = ((r == 0) ? isq2 : 1.0f) * 0.25f;
  float q0 = ((r == 0) ? 0.5f  : isq2) * 0.25f;
  const int qoff = (type < 4) ? 0 : 64;
  float H[8];
  #pragma unroll
  for (int u = 0; u < 8; u++) {
    float s = U[0] * CT(u, 0);
    #pragma unroll
    for (int x = 1; x < 8; x++) s = fmaf(U[x], CT(u, x), s);
    float su = (u == 0) ? q0 : q1;
    float F  = su * s;
    float qv = qtS[qoff + u * 8 + r];
    float rq = qrS[qoff + u * 8 + r];
    float c  = poly_round_f(F * rq);
    H[u] = su * (c * qv);
  }

  // Pass 3 (col IDCT)
  float Gv[8];
  #pragma unroll
  for (int x = 0; x < 8; x++) {
    float s = H[0] * CT(0, x);
    #pragma unroll
    for (int u = 1; u < 8; u++) s = fmaf(H[u], CT(u, x), s);
    Gv[x] = s;
  }

  // Transpose 2
  #pragma unroll
  for (int x = 0; x < 8; x++) trb[x * 9 + r] = Gv[x];
  __syncthreads();
  float P[8];
  #pragma unroll
  for (int v = 0; v < 8; v++) P[v] = trb[r * 9 + v];

  // Pass 4 (row IDCT), write decoded planes back
  float pix[8];
  #pragma unroll
  for (int y = 0; y < 8; y++) {
    float s = P[0] * CT(0, y);
    #pragma unroll
    for (int v = 1; v < 8; v++) s = fmaf(P[v], CT(v, y), s);
    pix[y] = s + 128.0f;
  }
  if (type < 4) {
    float* yp = yS + qrow * PITCH + col0;
    *(float4*)yp       = make_float4(pix[0], pix[1], pix[2], pix[3]);
    *(float4*)(yp + 4) = make_float4(pix[4], pix[5], pix[6], pix[7]);
  } else {
    float* cp = ((type == 4) ? cbS : crS) + r * PITCH + tt * 8;
    *(float4*)cp       = make_float4(pix[0], pix[1], pix[2], pix[3]);
    *(float4*)(cp + 4) = make_float4(pix[4], pix[5], pix[6], pix[7]);
  }
  __syncthreads();

  // ---- Phase 3: assemble RGB, diff_clip, rescale, store ----
  #pragma unroll
  for (int k = 0; k < 2; k++) {
    int q = t + 384 * k;
    if (q < 512) {
      int row = q >> 5;
      int c4  = (q & 31) * 4;
      float rr[4], gg[4], bb[4];
      #pragma unroll
      for (int l = 0; l < 4; l++) {
        int j  = c4 + l;
        int cc = (j >> 4) * 8 + ((j & 15) >> 1);
        float Y   = yS [row * PITCH + j];
        float cbv = cbS[(row >> 1) * PITCH + cc] - 128.0f;
        float crv = crS[(row >> 1) * PITCH + cc] - 128.0f;
        float R  = Y + 1.402f    * crv;
        float G  = Y - 0.344136f * cbv - 0.714136f * crv;
        float B  = Y + 1.772f    * cbv;
        R = diff_clip_f(R, 0.0f, 255.0f);
        G = diff_clip_f(G, 0.0f, 255.0f);
        B = diff_clip_f(B, 0.0f, 255.0f);
        rr[l] = fminf(fmaxf(R * 2.0f / 255.0f - 1.0f, -1.0f), 1.0f);
        gg[l] = fminf(fmaxf(G * 2.0f / 255.0f - 1.0f, -1.0f), 1.0f);
        bb[l] = fminf(fmaxf(B * 2.0f / 255.0f - 1.0f, -1.0f), 1.0f);
      }
      float* p = outb + (long)row * W + c4;
      *(float4*)p               = make_float4(rr[0], rr[1], rr[2], rr[3]);
      *(float4*)(p + plane)     = make_float4(gg[0], gg[1], gg[2], gg[3]);
      *(float4*)(p + 2 * plane) = make_float4(bb[0], bb[1], bb[2], bb[3]);
    }
  }
}

extern "C" void kernel_launch(void* const* d_in, const int* in_sizes, int n_in,
                              void* d_out, int out_size) {
  const float* in = (const float*)d_in[0];
  float* out = (float*)d_out;
  int B = in_sizes[0] / (3 * 512 * 512);
  dim3 grid(4, 32, B);
  jpeg_fused<<<grid, 384>>>(in, out);
}